// round 7
// baseline (speedup 1.0000x reference)
#include <cuda_runtime.h>
#include <stdint.h>

#define NN 50000
#define DD 128
#define RR 16
#define EE 1600000
#define NSEG (NN * RR)   // 800000 (dst-major, rel-minor segments)

// ---------------- device scratch (no allocs allowed) ----------------
__device__ __align__(16) float g_h1[(size_t)NN * DD];   // layer-1 output
__device__ int   g_cnt[NSEG];
__device__ __align__(16) float g_inv[NSEG];
__device__ int   g_off[NSEG + 1];
__device__ int   g_cursor[NSEG];
__device__ unsigned long long g_rec[EE];   // packed (dst | src<<20 | rel<<40)
__device__ unsigned int g_csr[EE];         // seg-sorted: src
__device__ int   g_is64;                   // 1 if edge arrays are int64, else int32

// ---------------- helpers ----------------
__device__ __forceinline__ float tf32r(float x) {
    uint32_t u;
    asm("cvt.rna.tf32.f32 %0, %1;" : "=r"(u) : "f"(x));
    return __uint_as_float(u);
}

__device__ __forceinline__ void mma8(float* c, const uint32_t* a, const uint32_t* b) {
    asm volatile(
        "mma.sync.aligned.m16n8k8.row.col.f32.tf32.tf32.f32 "
        "{%0,%1,%2,%3}, {%4,%5,%6,%7}, {%8,%9}, {%0,%1,%2,%3};"
        : "+f"(c[0]), "+f"(c[1]), "+f"(c[2]), "+f"(c[3])
        : "r"(a[0]), "r"(a[1]), "r"(a[2]), "r"(a[3]), "r"(b[0]), "r"(b[1]));
}

// ---------------- dtype detector ----------------
// int64 edge_type with values in [0,16) -> every odd 32-bit word is zero.
__global__ void detect_kernel(const unsigned int* __restrict__ et_words) {
    __shared__ int any_nonzero;
    if (threadIdx.x == 0) any_nonzero = 0;
    __syncthreads();
    for (int i = threadIdx.x; i < 2048; i += blockDim.x) {
        if (et_words[2 * i + 1] != 0u) any_nonzero = 1;
    }
    __syncthreads();
    if (threadIdx.x == 0) g_is64 = any_nonzero ? 0 : 1;
}

// ---------------- setup kernels (structure shared by both layers) -------------
__global__ void zero_cnt_kernel() {
    int i = blockIdx.x * blockDim.x + threadIdx.x;
    for (; i < NSEG; i += gridDim.x * blockDim.x) g_cnt[i] = 0;
}

__global__ void count_kernel(const void* __restrict__ ei_raw,
                             const void* __restrict__ et_raw) {
    const int is64 = g_is64;
    int e = blockIdx.x * blockDim.x + threadIdx.x;
    for (; e < EE; e += gridDim.x * blockDim.x) {
        int s, d, r;
        if (is64) {
            const long long* ei = (const long long*)ei_raw;
            const long long* et = (const long long*)et_raw;
            s = (int)ei[e];
            d = (int)ei[(size_t)EE + e];
            r = (int)et[e];
        } else {
            const int* ei = (const int*)ei_raw;
            const int* et = (const int*)et_raw;
            s = ei[e];
            d = ei[EE + e];
            r = et[e];
        }
        if ((unsigned)s >= NN || (unsigned)d >= NN || (unsigned)r >= RR) {
            g_rec[e] = ~0ull;
            continue;
        }
        g_rec[e] = (unsigned long long)d
                 | ((unsigned long long)s << 20)
                 | ((unsigned long long)r << 40);
        atomicAdd(&g_cnt[d * RR + r], 1);
    }
}

__global__ void inv_kernel() {
    int i = blockIdx.x * blockDim.x + threadIdx.x;
    for (; i < NSEG; i += gridDim.x * blockDim.x) {
        int c = g_cnt[i];
        g_inv[i] = 1.0f / (float)(c > 1 ? c : 1);
    }
}

// single-block exclusive scan over NSEG = 800000 segment counts
__global__ void scan_kernel() {
    __shared__ int part[1024];
    const int tid = threadIdx.x;
    const int CH = (NSEG + 1023) / 1024;  // 782
    int base = tid * CH;
    int s = 0;
    for (int j = 0; j < CH; j++) {
        int idx = base + j;
        if (idx < NSEG) s += g_cnt[idx];
    }
    part[tid] = s;
    __syncthreads();
    for (int ofs = 1; ofs < 1024; ofs <<= 1) {
        int add = (tid >= ofs) ? part[tid - ofs] : 0;
        __syncthreads();
        part[tid] += add;
        __syncthreads();
    }
    int excl = (tid > 0) ? part[tid - 1] : 0;
    int run = excl;
    for (int j = 0; j < CH; j++) {
        int idx = base + j;
        if (idx < NSEG) {
            g_off[idx] = run;
            g_cursor[idx] = run;
            run += g_cnt[idx];
        }
    }
    if (tid == 1023) g_off[NSEG] = part[1023];
}

__global__ void csr_kernel() {
    int e = blockIdx.x * blockDim.x + threadIdx.x;
    for (; e < EE; e += gridDim.x * blockDim.x) {
        unsigned long long rc = g_rec[e];
        if (rc == ~0ull) continue;
        int d = (int)(rc & 0xFFFFFu);
        int s = (int)((rc >> 20) & 0xFFFFFu);
        int r = (int)(rc >> 40);
        int pos = atomicAdd(&g_cursor[d * RR + r], 1);
        g_csr[pos] = (unsigned)s;
    }
}

// ---------------- fused agg + GEMM ----------------
// Per 128-row M-tile: for r in 0..16 (16 = root/self), build msg tile in smem
// (gather + mean-scale + tf32), mma against W_r chunk-by-chunk, accumulate in
// registers. Epilogue: + bias, relu, store. No g_msg materialization.
#define ASTR 132
#define BSTR 132
#define FUSED_SMEM ((128 * ASTR + 32 * BSTR) * 4)   // 84,480 bytes dynamic

__global__ void __launch_bounds__(256, 2)
fused_kernel(const float* __restrict__ Xext,
             const float* __restrict__ W,
             const float* __restrict__ root,
             const float* __restrict__ bias,
             float* __restrict__ Yext,
             int io_mode)  // bit0: input from g_h1; bit1: output to g_h1
{
    extern __shared__ float sm[];
    float* As = sm;                 // 128 x 132: msg tile (full K=128, tf32)
    float* Bs = sm + 128 * ASTR;    // 32 x 132:  W_r K-chunk

    const float* __restrict__ X = (io_mode & 1) ? (const float*)g_h1 : Xext;
    float* __restrict__ Y = (io_mode & 2) ? (float*)g_h1 : Yext;

    const int tid = threadIdx.x;
    const int lane = tid & 31;
    const int warp = tid >> 5;
    const int row0 = blockIdx.x * 128;
    const int wm = warp & 3;   // 4 warps over M (32 rows each)
    const int wn = warp >> 2;  // 2 warps over N (64 cols each)

    float acc[2][8][4];
#pragma unroll
    for (int mi = 0; mi < 2; mi++)
#pragma unroll
        for (int ni = 0; ni < 8; ni++)
#pragma unroll
            for (int q = 0; q < 4; q++) acc[mi][ni][q] = 0.0f;

    for (int r = 0; r < 17; r++) {
        __syncthreads();  // As safe to overwrite (prev rel's mma done)
        // ---- gather phase: warp w builds rows w*16 .. w*16+15 of msg tile ----
        for (int nn_ = 0; nn_ < 16; nn_++) {
            int nl = warp * 16 + nn_;
            int i = row0 + nl;
            float4 a = make_float4(0.f, 0.f, 0.f, 0.f);
            float iv = 0.0f;
            if (i < NN) {
                if (r < 16) {
                    int seg = i * RR + r;
                    int pb = __ldg(&g_off[seg]);
                    int pe = __ldg(&g_off[seg + 1]);
                    iv = __ldg(&g_inv[seg]);
                    for (int p = pb; p < pe; p++) {
                        int s = (int)__ldg(&g_csr[p]);
                        float4 v = *(const float4*)(X + (size_t)s * DD + lane * 4);
                        a.x += v.x; a.y += v.y; a.z += v.z; a.w += v.w;
                    }
                } else {  // self/root term: msg = x[i]
                    a = *(const float4*)(X + (size_t)i * DD + lane * 4);
                    iv = 1.0f;
                }
            }
            float4 o;
            o.x = tf32r(a.x * iv);
            o.y = tf32r(a.y * iv);
            o.z = tf32r(a.z * iv);
            o.w = tf32r(a.w * iv);
            *(float4*)(As + nl * ASTR + lane * 4) = o;
        }
        __syncthreads();  // msg tile complete

        const float* Wr = (r < 16) ? (W + (size_t)r * DD * DD) : root;
#pragma unroll
        for (int kc = 0; kc < 4; kc++) {
            if (kc > 0) __syncthreads();  // prev chunk's mma done reading Bs
            // ---- load Bs: rows kc*32 .. kc*32+31 of W_r ----
#pragma unroll
            for (int it = 0; it < 4; it++) {
                int j = tid + 256 * it;
                int rB = j >> 5;
                int cg = j & 31;
                float4 v = *(const float4*)(Wr + (size_t)(kc * 32 + rB) * DD + cg * 4);
                v.x = tf32r(v.x); v.y = tf32r(v.y); v.z = tf32r(v.z); v.w = tf32r(v.w);
                *(float4*)(Bs + rB * BSTR + cg * 4) = v;
            }
            __syncthreads();

            const uint32_t* Au = (const uint32_t*)As;
            const uint32_t* Bu = (const uint32_t*)Bs;
#pragma unroll
            for (int ks = 0; ks < 4; ks++) {
                int ka = kc * 32 + ks * 8;  // A col (full-K tile)
                int kb8 = ks * 8;           // B row (within chunk)
                uint32_t a[2][4];
#pragma unroll
                for (int mi = 0; mi < 2; mi++) {
                    int rb = wm * 32 + mi * 16 + (lane >> 2);
                    int cb = ka + (lane & 3);
                    a[mi][0] = Au[rb * ASTR + cb];
                    a[mi][1] = Au[(rb + 8) * ASTR + cb];
                    a[mi][2] = Au[rb * ASTR + cb + 4];
                    a[mi][3] = Au[(rb + 8) * ASTR + cb + 4];
                }
                uint32_t b[8][2];
#pragma unroll
                for (int ni = 0; ni < 8; ni++) {
                    int col = wn * 64 + ni * 8 + (lane >> 2);
                    int kb = kb8 + (lane & 3);
                    b[ni][0] = Bu[kb * BSTR + col];
                    b[ni][1] = Bu[(kb + 4) * BSTR + col];
                }
#pragma unroll
                for (int mi = 0; mi < 2; mi++)
#pragma unroll
                    for (int ni = 0; ni < 8; ni++)
                        mma8(acc[mi][ni], a[mi], b[ni]);
            }
        }
    }

    // ---- epilogue: + bias, relu, store ----
#pragma unroll
    for (int mi = 0; mi < 2; mi++) {
        int r0 = row0 + wm * 32 + mi * 16 + (lane >> 2);
#pragma unroll
        for (int ni = 0; ni < 8; ni++) {
            int cc = wn * 64 + ni * 8 + (lane & 3) * 2;
            float bi0 = __ldg(&bias[cc]);
            float bi1 = __ldg(&bias[cc + 1]);
            if (r0 < NN) {
                float y0 = fmaxf(acc[mi][ni][0] + bi0, 0.0f);
                float y1 = fmaxf(acc[mi][ni][1] + bi1, 0.0f);
                *(float2*)(Y + (size_t)r0 * DD + cc) = make_float2(y0, y1);
            }
            if (r0 + 8 < NN) {
                float y2 = fmaxf(acc[mi][ni][2] + bi0, 0.0f);
                float y3 = fmaxf(acc[mi][ni][3] + bi1, 0.0f);
                *(float2*)(Y + (size_t)(r0 + 8) * DD + cc) = make_float2(y2, y3);
            }
        }
    }
}

// ---------------- launch ----------------
extern "C" void kernel_launch(void* const* d_in, const int* in_sizes, int n_in,
                              void* d_out, int out_size) {
    const float* x     = (const float*)d_in[0];
    const void*  ei    = d_in[1];   // int32 or int64, detected on device
    const void*  et    = d_in[2];
    const float* W1    = (const float*)d_in[3];
    const float* root1 = (const float*)d_in[4];
    const float* b1    = (const float*)d_in[5];
    const float* W2    = (const float*)d_in[6];
    const float* root2 = (const float*)d_in[7];
    const float* b2    = (const float*)d_in[8];
    float* out         = (float*)d_out;

    // opt in to >48KB dynamic smem (non-stream API; idempotent per call)
    cudaFuncSetAttribute(fused_kernel,
                         cudaFuncAttributeMaxDynamicSharedMemorySize, FUSED_SMEM);

    // structure (shared by both layers)
    detect_kernel<<<1, 256>>>((const unsigned int*)et);
    zero_cnt_kernel<<<1024, 256>>>();
    count_kernel<<<2048, 256>>>(ei, et);
    inv_kernel<<<1024, 256>>>();
    scan_kernel<<<1, 1024>>>();
    csr_kernel<<<2048, 256>>>();

    const int blocks = (NN + 127) / 128;  // 391

    // layer 1: read x, write h1 (internal)
    fused_kernel<<<blocks, 256, FUSED_SMEM>>>(x, W1, root1, b1, out, /*io_mode=*/2);
    // layer 2: read h1 (internal), write d_out
    fused_kernel<<<blocks, 256, FUSED_SMEM>>>(nullptr, W2, root2, b2, out, /*io_mode=*/1);
}